// round 6
// baseline (speedup 1.0000x reference)
#include <cuda_runtime.h>
#include <cuda_bf16.h>
#include <math.h>
#include <algorithm>
#include <cstdint>

// ---------------- problem constants ----------------
#define BATCH 2
#define LSEQ  196
#define EMBED 768
#define DIMM  3072      // 4*EMBED
#define DINN  6144      // 2*DIMM
#define XRW   12288     // 2*DINN
#define DTR   192
#define DST   16
#define NTOK  392       // BATCH*LSEQ
#define PADM  512       // padded row count for 128-row M tiles

// ---------------- scratch (device globals; no allocs allowed) ----------------
__device__ float g_patches[PADM * EMBED];
__device__ float g_xe     [PADM * EMBED];
__device__ float g_vec    [BATCH * EMBED];
__device__ float g_xm     [PADM * DIMM];
__device__ float g_xln    [PADM * DIMM];
__device__ float g_xr     [PADM * XRW];
__device__ float g_xs     [PADM * DINN];
__device__ float g_dbl    [PADM * 224];
__device__ float g_dt     [PADM * DINN];
__device__ float g_y      [PADM * DINN];
__device__ float g_pr     [PADM * EMBED];
__device__ float g_prln   [NTOK * EMBED];
__device__ int   g_sp[LSEQ], g_ra[LSEQ], g_bo[LSEQ];

// ================= bf16 mma.sync GEMM (on-the-fly hi/lo split) =================
// C[M,N] = A[Mpad,K](fp32) * W[N,K]^T(fp32), 3-term hi/lo bf16 split.
// Block tile 128x128, BK=32 fp32. 8 warps each 64x32 (m16n8k16 fragments).
// Double-buffered SMEM stages, one __syncthreads per chunk.
// grid = (Ntiles, 4, zsplit). modes: 0 store, 1 +bias, 2 atomicAdd, 3 softplus(+bias).
#define PLA  10240           // plane stride: 128 rows * 80B
#define ROWB 80              // smem row stride (5x16B -> conflict-free ldmatrix)
#define STG  (4 * PLA)       // stage stride (Ah, Al, Bh, Bl planes)
#define GSMEM (2 * STG)      // 81920 bytes dynamic smem

__device__ __forceinline__ uint32_t smem_u32(const void* p) {
    uint32_t a;
    asm("{ .reg .u64 t; cvta.to.shared.u64 t, %1; cvt.u32.u64 %0, t; }" : "=r"(a) : "l"(p));
    return a;
}
__device__ __forceinline__ uint32_t pack_bf(__nv_bfloat16 a, __nv_bfloat16 b) {
    return (uint32_t)__bfloat16_as_ushort(a) | ((uint32_t)__bfloat16_as_ushort(b) << 16);
}
#define LDSM_X4(r, addr) \
    asm volatile("ldmatrix.sync.aligned.m8n8.x4.shared.b16 {%0,%1,%2,%3}, [%4];" \
        : "=r"((r)[0]), "=r"((r)[1]), "=r"((r)[2]), "=r"((r)[3]) : "r"(addr))
#define MMA16816(d, a, b) \
    asm volatile("mma.sync.aligned.m16n8k16.row.col.f32.bf16.bf16.f32 " \
        "{%0,%1,%2,%3}, {%4,%5,%6,%7}, {%8,%9}, {%0,%1,%2,%3};" \
        : "+f"((d)[0]), "+f"((d)[1]), "+f"((d)[2]), "+f"((d)[3]) \
        : "r"((a)[0]), "r"((a)[1]), "r"((a)[2]), "r"((a)[3]), "r"((b)[0]), "r"((b)[1]))

__global__ __launch_bounds__(256, 1)
void gemm_mma(const float* __restrict__ A, int lda,
              const float* __restrict__ W, int ldw,
              float* __restrict__ C, int ldc,
              const float* __restrict__ bias,
              int Nvalid, int Ktot, int mode)
{
    extern __shared__ __align__(16) char dynsmem[];
    const int tid  = threadIdx.x;
    const int wid  = tid >> 5;
    const int lane = tid & 31;
    const int wm = wid & 1;        // 2 warp rows of 64
    const int wn = wid >> 1;       // 4 warp cols of 32
    const int m0 = blockIdx.y * 128;
    const int n0 = blockIdx.x * 128;
    const int nk = Ktot / (32 * (int)gridDim.z);
    const int kbeg = blockIdx.z * nk * 32;

    const uint32_t sb = smem_u32(dynsmem);

    // ---- staging roles: each thread owns one row, half the k-chunk ----
    const int lrow = tid >> 1;
    const int half = tid & 1;
    const float* Ap = A + (size_t)(m0 + lrow) * lda + kbeg + half * 16;
    const bool bvalid = (n0 + lrow) < Nvalid;
    const float* Wp = bvalid ? (W + (size_t)(n0 + lrow) * ldw + kbeg + half * 16) : nullptr;

    float4 a_st[4], b_st[4];
    const float4 zf4 = make_float4(0.f, 0.f, 0.f, 0.f);

    auto load_stage = [&](int c) {
        const float* ap = Ap + c * 32;
        a_st[0] = *(const float4*)(ap + 0);
        a_st[1] = *(const float4*)(ap + 4);
        a_st[2] = *(const float4*)(ap + 8);
        a_st[3] = *(const float4*)(ap + 12);
        if (bvalid) {
            const float* wp = Wp + c * 32;
            b_st[0] = *(const float4*)(wp + 0);
            b_st[1] = *(const float4*)(wp + 4);
            b_st[2] = *(const float4*)(wp + 8);
            b_st[3] = *(const float4*)(wp + 12);
        } else { b_st[0] = b_st[1] = b_st[2] = b_st[3] = zf4; }
    };
    auto split_store = [&](const float4* src, uint32_t hiB, uint32_t loB) {
        float f[16];
        *(float4*)(f + 0)  = src[0]; *(float4*)(f + 4)  = src[1];
        *(float4*)(f + 8)  = src[2]; *(float4*)(f + 12) = src[3];
        #pragma unroll
        for (int cc = 0; cc < 2; cc++) {
            uint32_t hw[4], lw[4];
            #pragma unroll
            for (int j = 0; j < 4; j++) {
                float v0 = f[cc * 8 + 2 * j], v1 = f[cc * 8 + 2 * j + 1];
                __nv_bfloat16 h0 = __float2bfloat16(v0), h1 = __float2bfloat16(v1);
                hw[j] = pack_bf(h0, h1);
                lw[j] = pack_bf(__float2bfloat16(v0 - __bfloat162float(h0)),
                                __float2bfloat16(v1 - __bfloat162float(h1)));
            }
            uint32_t off = lrow * ROWB + (half * 2 + cc) * 16;
            asm volatile("st.shared.v4.b32 [%0], {%1,%2,%3,%4};" ::
                "r"(hiB + off), "r"(hw[0]), "r"(hw[1]), "r"(hw[2]), "r"(hw[3]));
            asm volatile("st.shared.v4.b32 [%0], {%1,%2,%3,%4};" ::
                "r"(loB + off), "r"(lw[0]), "r"(lw[1]), "r"(lw[2]), "r"(lw[3]));
        }
    };
    auto store_stage = [&](int s) {
        uint32_t base = sb + s * STG;
        split_store(a_st, base, base + PLA);
        split_store(b_st, base + 2 * PLA, base + 3 * PLA);
    };

    float d[4][4][4];
    #pragma unroll
    for (int i = 0; i < 4; i++)
        #pragma unroll
        for (int j = 0; j < 4; j++)
            #pragma unroll
            for (int q = 0; q < 4; q++) d[i][j][q] = 0.f;

    // ldmatrix base offsets (per thread)
    const int arow = wm * 64 + (lane & 15);
    const int asel = lane >> 4;
    const int brow = wn * 32 + (lane >> 4) * 8 + (lane & 7);
    const int bsel = (lane >> 3) & 1;

    load_stage(0);
    store_stage(0);
    __syncthreads();

    for (int c = 0; c < nk; c++) {
        const int cur = c & 1;
        if (c + 1 < nk) load_stage(c + 1);

        const uint32_t base = sb + cur * STG;
        const uint32_t sAh = base, sAl = base + PLA;
        const uint32_t sBh = base + 2 * PLA, sBl = base + 3 * PLA;

        #pragma unroll
        for (int ks = 0; ks < 2; ks++) {
            uint32_t ah[4][4], al[4][4], bh[4][2], bl[4][2];
            #pragma unroll
            for (int mt = 0; mt < 4; mt++) {
                uint32_t off = (arow + mt * 16) * ROWB + (ks * 2 + asel) * 16;
                LDSM_X4(ah[mt], sAh + off);
                LDSM_X4(al[mt], sAl + off);
            }
            #pragma unroll
            for (int np = 0; np < 2; np++) {
                uint32_t off = (brow + np * 16) * ROWB + (ks * 2 + bsel) * 16;
                uint32_t th[4], tl[4];
                LDSM_X4(th, sBh + off);
                LDSM_X4(tl, sBl + off);
                bh[2 * np][0] = th[0]; bh[2 * np][1] = th[1];
                bh[2 * np + 1][0] = th[2]; bh[2 * np + 1][1] = th[3];
                bl[2 * np][0] = tl[0]; bl[2 * np][1] = tl[1];
                bl[2 * np + 1][0] = tl[2]; bl[2 * np + 1][1] = tl[3];
            }
            #pragma unroll
            for (int mt = 0; mt < 4; mt++)
                #pragma unroll
                for (int nt = 0; nt < 4; nt++) {
                    MMA16816(d[mt][nt], ah[mt], bh[nt]);
                    MMA16816(d[mt][nt], ah[mt], bl[nt]);
                    MMA16816(d[mt][nt], al[mt], bh[nt]);
                }
        }
        if (c + 1 < nk) {
            store_stage((c + 1) & 1);
            __syncthreads();
        }
    }

    // ---- epilogue ----
    const int g = lane >> 2, q = lane & 3;
    #pragma unroll
    for (int mt = 0; mt < 4; mt++) {
        int r0 = m0 + wm * 64 + mt * 16 + g;
        #pragma unroll
        for (int nt = 0; nt < 4; nt++) {
            int c0 = n0 + wn * 32 + nt * 8 + q * 2;
            if (c0 >= Nvalid) continue;
            bool c1v = (c0 + 1) < Nvalid;
            float v00 = d[mt][nt][0], v01 = d[mt][nt][1];
            float v10 = d[mt][nt][2], v11 = d[mt][nt][3];
            float* p0 = C + (size_t)r0 * ldc + c0;
            float* p1 = C + (size_t)(r0 + 8) * ldc + c0;
            if (mode == 2) {
                atomicAdd(p0, v00); if (c1v) atomicAdd(p0 + 1, v01);
                atomicAdd(p1, v10); if (c1v) atomicAdd(p1 + 1, v11);
            } else {
                if (mode == 1) {
                    v00 += bias[c0]; v10 += bias[c0];
                    if (c1v) { v01 += bias[c0 + 1]; v11 += bias[c0 + 1]; }
                } else if (mode == 3) {
                    float b0 = bias[c0], b1 = c1v ? bias[c0 + 1] : 0.f;
                    float t;
                    t = v00 + b0; v00 = (t > 20.f) ? t : log1pf(expf(t));
                    t = v10 + b0; v10 = (t > 20.f) ? t : log1pf(expf(t));
                    t = v01 + b1; v01 = (t > 20.f) ? t : log1pf(expf(t));
                    t = v11 + b1; v11 = (t > 20.f) ? t : log1pf(expf(t));
                }
                if (c1v) {
                    *(float2*)p0 = make_float2(v00, v01);
                    *(float2*)p1 = make_float2(v10, v11);
                } else { *p0 = v00; *p1 = v10; }
            }
        }
    }
}

// ================= elementwise / misc kernels =================
__global__ void im2col_kernel(const float* __restrict__ x) {
    int idx = blockIdx.x * blockDim.x + threadIdx.x;
    if (idx >= NTOK * EMBED) return;
    int col = idx % EMBED;
    int row = idx / EMBED;
    int b = row / LSEQ, l = row % LSEQ;
    int ph = l / 14, pw = l % 14;
    int c = col / 256;
    int i = (col % 256) / 16;
    int j = col % 16;
    size_t src = (((size_t)b * 3 + c) * 224 + (ph * 16 + i)) * 224 + (pw * 16 + j);
    g_patches[row * EMBED + col] = x[src];
}

__global__ void abcde_kernel(const float* __restrict__ f, const float* __restrict__ w,
                             const float* __restrict__ b) {
    int idx = blockIdx.x * blockDim.x + threadIdx.x;
    if (idx >= BATCH * EMBED) return;
    int bb = idx / EMBED, e = idx % EMBED;
    float s = b[e];
    #pragma unroll
    for (int k = 0; k < 5; k++) s += f[bb * 5 + k] * w[e * 5 + k];
    g_vec[idx] = s;
}

__global__ void patch_epi_kernel(const float* __restrict__ pb, const float* __restrict__ pos) {
    int idx = blockIdx.x * blockDim.x + threadIdx.x;
    if (idx >= NTOK * EMBED) return;
    int e = idx % EMBED;
    int row = idx / EMBED;
    int b = row / LSEQ, l = row % LSEQ;
    g_xe[idx] += pb[e] + pos[l * EMBED + e] + g_vec[b * EMBED + e];
}

__global__ void gather_kernel() {
    int idx = blockIdx.x * blockDim.x + threadIdx.x;
    if (idx >= NTOK * DIMM) return;
    int e = idx % EMBED;
    int c = (idx / EMBED) & 3;
    int l = (idx / DIMM) % LSEQ;
    int b = idx / (DIMM * LSEQ);
    int src_l = (c == 0) ? g_sp[l] : (c == 1) ? g_ra[l] : (c == 2) ? g_bo[l] : l;
    g_xm[idx] = g_xe[((size_t)b * LSEQ + src_l) * EMBED + e];
}

__global__ void ln_kernel(const float* __restrict__ x, const float* __restrict__ inb,
                          const float* __restrict__ w, const float* __restrict__ b,
                          float* __restrict__ out, int D) {
    int row = blockIdx.x;
    const float* xr = x + (size_t)row * D;
    float* orow = out + (size_t)row * D;
    __shared__ float sh[256];
    __shared__ float s_mean, s_inv;
    int tid = threadIdx.x;
    float s = 0.f;
    for (int i = tid; i < D; i += 256) s += xr[i] + (inb ? inb[i] : 0.f);
    sh[tid] = s; __syncthreads();
    for (int o = 128; o > 0; o >>= 1) { if (tid < o) sh[tid] += sh[tid + o]; __syncthreads(); }
    if (tid == 0) s_mean = sh[0] / (float)D;
    __syncthreads();
    float m = s_mean;
    float v2 = 0.f;
    for (int i = tid; i < D; i += 256) {
        float t = xr[i] + (inb ? inb[i] : 0.f) - m;
        v2 += t * t;
    }
    sh[tid] = v2; __syncthreads();
    for (int o = 128; o > 0; o >>= 1) { if (tid < o) sh[tid] += sh[tid + o]; __syncthreads(); }
    if (tid == 0) s_inv = 1.f / sqrtf(sh[0] / (float)D + 1e-5f);
    __syncthreads();
    float inv = s_inv;
    for (int i = tid; i < D; i += 256) {
        float t = (xr[i] + (inb ? inb[i] : 0.f) - m) * inv;
        orow[i] = t * w[i] + b[i];
    }
}

__global__ void conv_silu_kernel(const float* __restrict__ w, const float* __restrict__ bias) {
    int idx = blockIdx.x * blockDim.x + threadIdx.x;
    if (idx >= NTOK * DINN) return;
    int d = idx % DINN;
    int t = (idx / DINN) % LSEQ;
    int b = idx / (DINN * LSEQ);
    const float* wd = w + (size_t)d * 4;
    float acc = bias[d];
    size_t rb = ((size_t)b * LSEQ) * XRW + d;
    #pragma unroll
    for (int k = 0; k < 4; k++) {
        int tt = t - 3 + k;
        if (tt >= 0) acc = fmaf(wd[k], g_xr[rb + (size_t)tt * XRW], acc);
    }
    g_xs[idx] = acc / (1.f + __expf(-acc));
}

__global__ void scan_kernel(const float* __restrict__ alog, const float* __restrict__ Dp) {
    int tid = threadIdx.x;
    int n  = tid & 15;
    int ci = tid >> 4;
    int blk = blockIdx.x;
    int b = blk / 384;
    int d = (blk % 384) * 16 + ci;

    float Ac = -__expf(alog[(size_t)d * DST + n]);
    float Dv = Dp[d];
    float st = 0.f;
    size_t base = (size_t)b * LSEQ;
    for (int t = 0; t < LSEQ; t++) {
        size_t row = base + t;
        float dtv = g_dt[row * DINN + d];
        float xv  = g_xs[row * DINN + d];
        float Bv  = g_dbl[row * 224 + 192 + n];
        float Cv  = g_dbl[row * 224 + 208 + n];
        st = fmaf(st, __expf(dtv * Ac), dtv * Bv * xv);
        float yp = st * Cv;
        yp += __shfl_down_sync(0xffffffffu, yp, 8, 16);
        yp += __shfl_down_sync(0xffffffffu, yp, 4, 16);
        yp += __shfl_down_sync(0xffffffffu, yp, 2, 16);
        yp += __shfl_down_sync(0xffffffffu, yp, 1, 16);
        if (n == 0) {
            float r = g_xr[row * XRW + DINN + d];
            float yf = fmaf(xv, Dv, yp);
            yf = yf * (r / (1.f + __expf(-r)));
            g_y[row * DINN + d] = yf;
        }
    }
}

__global__ void mean_kernel(float* __restrict__ out) {
    int idx = blockIdx.x * blockDim.x + threadIdx.x;
    if (idx >= BATCH * EMBED) return;
    int b = idx / EMBED, e = idx % EMBED;
    float s = 0.f;
    for (int t = 0; t < LSEQ; t++)
        s += g_prln[((size_t)b * LSEQ + t) * EMBED + e];
    out[idx] = s / (float)LSEQ;
}

// ---------------- host: permutation index construction (mirrors numpy) ------
static void build_spiral(int* sp) {
    bool seen[LSEQ] = {false};
    int cnt = 0;
    for (int r = 0; r < 14; r++) {
        int n = (2 * r > 8) ? 2 * r : 8;
        double step = (2.0 * M_PI) / (double)n;
        for (int k = 0; k < n; k++) {
            double ang = (double)k * step;
            int h = (int)(7.0 + (double)r * cos(ang));
            int w = (int)(7.0 + (double)r * sin(ang));
            if (h >= 0 && h < 14 && w >= 0 && w < 14) {
                int i = h * 14 + w;
                if (!seen[i]) { seen[i] = true; sp[cnt++] = i; }
            }
        }
    }
    for (int i = 0; i < LSEQ; i++) if (!seen[i]) sp[cnt++] = i;
}
struct RItem { double d, a; int i; };
static void build_radial(int* ra) {
    RItem items[LSEQ];
    for (int h = 0; h < 14; h++)
        for (int w = 0; w < 14; w++) {
            int i = h * 14 + w;
            double dy = (double)(h - 7), dx = (double)(w - 7);
            items[i].d = sqrt(dy * dy + dx * dx);
            items[i].a = atan2(dy, dx);
            items[i].i = i;
        }
    std::stable_sort(items, items + LSEQ, [](const RItem& x, const RItem& y) {
        if (x.d != y.d) return x.d > y.d;
        return x.a < y.a;
    });
    for (int i = 0; i < LSEQ; i++) ra[i] = items[i].i;
}
static void build_boundary(int* bo) {
    int cnt = 0;
    for (int h = 0; h < 14; h++)
        for (int w = 0; w < 14; w++)
            if (h == 0 || h == 13 || w == 0 || w == 13) bo[cnt++] = h * 14 + w;
    for (int h = 0; h < 14; h++)
        for (int w = 0; w < 14; w++)
            if (!(h == 0 || h == 13 || w == 0 || w == 13)) bo[cnt++] = h * 14 + w;
}

// ---------------- launcher ----------------
extern "C" void kernel_launch(void* const* d_in, const int* in_sizes, int n_in,
                              void* d_out, int out_size) {
    const float* x       = (const float*)d_in[0];
    const float* abf     = (const float*)d_in[1];
    const float* patch_w = (const float*)d_in[2];
    const float* patch_b = (const float*)d_in[3];
    const float* pos     = (const float*)d_in[4];
    const float* aw      = (const float*)d_in[5];
    const float* ab      = (const float*)d_in[6];
    const float* ln_w    = (const float*)d_in[7];
    const float* ln_b    = (const float*)d_in[8];
    const float* inw     = (const float*)d_in[9];
    const float* convw   = (const float*)d_in[10];
    const float* convb   = (const float*)d_in[11];
    const float* xpw     = (const float*)d_in[12];
    const float* dtw     = (const float*)d_in[13];
    const float* alog    = (const float*)d_in[14];
    const float* dpar    = (const float*)d_in[15];
    const float* outw    = (const float*)d_in[16];
    const float* projw   = (const float*)d_in[17];
    const float* projb   = (const float*)d_in[18];
    const float* normw   = (const float*)d_in[19];
    const float* normb   = (const float*)d_in[20];
    const float* dtb     = (const float*)d_in[21];

    static int hsp[LSEQ], hra[LSEQ], hbo[LSEQ];
    build_spiral(hsp);
    build_radial(hra);
    build_boundary(hbo);
    cudaMemcpyToSymbolAsync(g_sp, hsp, sizeof(hsp), 0, cudaMemcpyHostToDevice, 0);
    cudaMemcpyToSymbolAsync(g_ra, hra, sizeof(hra), 0, cudaMemcpyHostToDevice, 0);
    cudaMemcpyToSymbolAsync(g_bo, hbo, sizeof(hbo), 0, cudaMemcpyHostToDevice, 0);

    cudaFuncSetAttribute(gemm_mma, cudaFuncAttributeMaxDynamicSharedMemorySize, GSMEM);

    void *p_patches, *p_xe, *p_xm, *p_xln, *p_xr, *p_xs, *p_dbl, *p_dt, *p_y, *p_pr, *p_prln;
    cudaGetSymbolAddress(&p_patches, g_patches);
    cudaGetSymbolAddress(&p_xe, g_xe);
    cudaGetSymbolAddress(&p_xm, g_xm);
    cudaGetSymbolAddress(&p_xln, g_xln);
    cudaGetSymbolAddress(&p_xr, g_xr);
    cudaGetSymbolAddress(&p_xs, g_xs);
    cudaGetSymbolAddress(&p_dbl, g_dbl);
    cudaGetSymbolAddress(&p_dt, g_dt);
    cudaGetSymbolAddress(&p_y, g_y);
    cudaGetSymbolAddress(&p_pr, g_pr);
    cudaGetSymbolAddress(&p_prln, g_prln);

    const int T256 = 256;
    const int PAD = PADM - NTOK;

    // zero pad rows of every GEMM A-operand buffer
    cudaMemsetAsync((float*)p_patches + (size_t)NTOK * EMBED, 0, (size_t)PAD * EMBED * 4, 0);
    cudaMemsetAsync((float*)p_xln     + (size_t)NTOK * DIMM,  0, (size_t)PAD * DIMM  * 4, 0);
    cudaMemsetAsync((float*)p_xs      + (size_t)NTOK * DINN,  0, (size_t)PAD * DINN  * 4, 0);
    cudaMemsetAsync((float*)p_y       + (size_t)NTOK * DINN,  0, (size_t)PAD * DINN  * 4, 0);
    cudaMemsetAsync((float*)p_xm      + (size_t)NTOK * DIMM,  0, (size_t)PAD * DIMM  * 4, 0);

    // patch embedding + epilogue
    im2col_kernel<<<(NTOK * EMBED + T256 - 1) / T256, T256>>>(x);
    abcde_kernel<<<(BATCH * EMBED + T256 - 1) / T256, T256>>>(abf, aw, ab);
    cudaMemsetAsync(p_xe, 0, (size_t)PADM * EMBED * 4, 0);
    gemm_mma<<<dim3(6, 4, 3), T256, GSMEM>>>((const float*)p_patches, EMBED,
                                             patch_w, EMBED,
                                             (float*)p_xe, EMBED, nullptr, EMBED, EMBED, 2);
    patch_epi_kernel<<<(NTOK * EMBED + T256 - 1) / T256, T256>>>(patch_b, pos);
    gather_kernel<<<(NTOK * DIMM + T256 - 1) / T256, T256>>>();

    for (int l = 0; l < 2; l++) {
        ln_kernel<<<NTOK, T256>>>((const float*)p_xm, nullptr,
                                  ln_w + (size_t)l * DIMM, ln_b + (size_t)l * DIMM,
                                  (float*)p_xln, DIMM);
        // in_proj: (512,3072) x (12288,3072)^T -> xr (store)
        gemm_mma<<<dim3(96, 4, 1), T256, GSMEM>>>((const float*)p_xln, DIMM,
                                                  inw + (size_t)l * XRW * DIMM, DIMM,
                                                  (float*)p_xr, XRW, nullptr, XRW, DIMM, 0);
        conv_silu_kernel<<<(NTOK * DINN + T256 - 1) / T256, T256>>>(
            convw + (size_t)l * DINN * 4, convb + (size_t)l * DINN);
        // x_proj: split-K 12, atomic
        cudaMemsetAsync(p_dbl, 0, (size_t)PADM * 224 * 4, 0);
        gemm_mma<<<dim3(2, 4, 12), T256, GSMEM>>>((const float*)p_xs, DINN,
                                                  xpw + (size_t)l * 224 * DINN, DINN,
                                                  (float*)p_dbl, 224, nullptr, 224, DINN, 2);
        // dt_proj + softplus(+bias): A = dbl[:, :192] (lda=224)
        gemm_mma<<<dim3(48, 4, 1), T256, GSMEM>>>((const float*)p_dbl, 224,
                                                  dtw + (size_t)l * DINN * DTR, DTR,
                                                  (float*)p_dt, DINN,
                                                  dtb + (size_t)l * DINN, DINN, DTR, 3);
        scan_kernel<<<768, T256>>>(alog + (size_t)l * DINN * DST,
                                   dpar + (size_t)l * DINN);
        // out_proj residual accumulate into xm, split-K 2, atomic
        gemm_mma<<<dim3(24, 4, 2), T256, GSMEM>>>((const float*)p_y, DINN,
                                                  outw + (size_t)l * DIMM * DINN, DINN,
                                                  (float*)p_xm, DIMM, nullptr, DIMM, DINN, 2);
    }

    // final projection, split-K 6, atomic
    cudaMemsetAsync(p_pr, 0, (size_t)PADM * EMBED * 4, 0);
    gemm_mma<<<dim3(6, 4, 6), T256, GSMEM>>>((const float*)p_xm, DIMM,
                                             projw, DIMM,
                                             (float*)p_pr, EMBED, nullptr, EMBED, DIMM, 2);
    ln_kernel<<<NTOK, T256>>>((const float*)p_pr, projb, normw, normb,
                              (float*)p_prln, EMBED);
    mean_kernel<<<(BATCH * EMBED + T256 - 1) / T256, T256>>>((float*)d_out);
}

// round 9
// speedup vs baseline: 1.0585x; 1.0585x over previous
#include <cuda_runtime.h>
#include <cuda_bf16.h>
#include <math.h>
#include <algorithm>
#include <cstdint>

// ---------------- problem constants ----------------
#define BATCH 2
#define LSEQ  196
#define EMBED 768
#define DIMM  3072      // 4*EMBED
#define DINN  6144      // 2*DIMM
#define XRW   12288     // 2*DINN
#define DTR   192
#define DST   16
#define NTOK  392       // BATCH*LSEQ
#define PADM  512       // padded row count for 128-row M tiles

// ---------------- fp32 scratch ----------------
__device__ float g_xe     [PADM * EMBED];
__device__ float g_vec    [BATCH * EMBED];
__device__ float g_xm     [PADM * DIMM];
__device__ float g_xr     [PADM * XRW];
__device__ float g_xs     [PADM * DINN];
__device__ float g_dbl    [PADM * 224];
__device__ float g_dt     [PADM * DINN];
__device__ float g_pr     [PADM * EMBED];
__device__ float g_prln   [NTOK * EMBED];
__device__ int   g_sp[LSEQ], g_ra[LSEQ], g_bo[LSEQ];

// ---------------- bf16 hi/lo planes: activations ----------------
__device__ __nv_bfloat16 g_pah [PADM * EMBED], g_pal [PADM * EMBED];
__device__ __nv_bfloat16 g_xlnh[PADM * DIMM],  g_xlnl[PADM * DIMM];
__device__ __nv_bfloat16 g_xsh [PADM * DINN],  g_xsl [PADM * DINN];
__device__ __nv_bfloat16 g_yh  [PADM * DINN],  g_yl  [PADM * DINN];
__device__ __nv_bfloat16 g_dblh[PADM * 224],   g_dbll[PADM * 224];
__device__ __nv_bfloat16 g_xmh [PADM * DIMM],  g_xml [PADM * DIMM];

// ---------------- bf16 hi/lo planes: weights ----------------
#define SZ_INW  (2 * XRW * DIMM)
#define SZ_OUTW (2 * DIMM * DINN)
#define SZ_XPW  (2 * 224 * DINN)
#define SZ_DTW  (2 * DINN * DTR)
#define SZ_PRW  (EMBED * DIMM)
#define SZ_PAW  (EMBED * EMBED)
__device__ __nv_bfloat16 g_wih[SZ_INW],  g_wil[SZ_INW];
__device__ __nv_bfloat16 g_woh[SZ_OUTW], g_wol[SZ_OUTW];
__device__ __nv_bfloat16 g_wxh[SZ_XPW],  g_wxl[SZ_XPW];
__device__ __nv_bfloat16 g_wdh[SZ_DTW],  g_wdl[SZ_DTW];
__device__ __nv_bfloat16 g_wph[SZ_PRW],  g_wpl[SZ_PRW];
__device__ __nv_bfloat16 g_wch[SZ_PAW],  g_wcl[SZ_PAW];

// ---------------- helpers ----------------
__device__ __forceinline__ uint32_t smem_u32(const void* p) {
    uint32_t a;
    asm("{ .reg .u64 t; cvta.to.shared.u64 t, %1; cvt.u32.u64 %0, t; }" : "=r"(a) : "l"(p));
    return a;
}
__device__ __forceinline__ uint32_t pack_bf(__nv_bfloat16 a, __nv_bfloat16 b) {
    return (uint32_t)__bfloat16_as_ushort(a) | ((uint32_t)__bfloat16_as_ushort(b) << 16);
}
__device__ __forceinline__ void split2(float a, float b, uint32_t& h, uint32_t& l) {
    __nv_bfloat16 ha = __float2bfloat16(a), hb = __float2bfloat16(b);
    h = pack_bf(ha, hb);
    l = pack_bf(__float2bfloat16(a - __bfloat162float(ha)),
                __float2bfloat16(b - __bfloat162float(hb)));
}

// ---------------- streaming hi/lo split convert (8 floats / thread / iter) ----
__global__ void cvt_kernel(const float4* __restrict__ src,
                           uint4* __restrict__ hi, uint4* __restrict__ lo, int n8) {
    int i = blockIdx.x * blockDim.x + threadIdx.x;
    int stride = gridDim.x * blockDim.x;
    for (; i < n8; i += stride) {
        float4 v0 = src[2 * i], v1 = src[2 * i + 1];
        uint4 H, L;
        split2(v0.x, v0.y, H.x, L.x);
        split2(v0.z, v0.w, H.y, L.y);
        split2(v1.x, v1.y, H.z, L.z);
        split2(v1.z, v1.w, H.w, L.w);
        hi[i] = H; lo[i] = L;
    }
}

// ================= bf16 mma.sync GEMM, cp.async 4-stage pipeline =================
// C[M,N] = (Ah+Al)[Mpad,K] * ((Bh+Bl)[N,K])^T, 3-term split (drop Al*Bl).
// Block tile 128x128, BK=32. 8 warps each 64x32 (m16n8k16).
// modes: 0 store, 1 +bias, 2 atomicAdd, 3 softplus(+bias).
#define ROWB 80              // smem row stride bytes (64B data + 16B skew)
#define PLA  10240           // plane: 128 rows * ROWB
#define STG  (4 * PLA)       // stage: Ah, Al, Bh, Bl planes = 40960 B
#define NSTG 4
#define GSMEM (NSTG * STG)   // 163840 B dynamic smem

#define CP_ASYNC(dst, src, sz) \
    asm volatile("cp.async.cg.shared.global [%0], [%1], 16, %2;" \
        :: "r"(dst), "l"(src), "r"(sz))
#define CP_COMMIT() asm volatile("cp.async.commit_group;" ::: "memory")
#define CP_WAIT2()  asm volatile("cp.async.wait_group 2;" ::: "memory")

#define LDSM_X4(r, addr) \
    asm volatile("ldmatrix.sync.aligned.m8n8.x4.shared.b16 {%0,%1,%2,%3}, [%4];" \
        : "=r"((r)[0]), "=r"((r)[1]), "=r"((r)[2]), "=r"((r)[3]) : "r"(addr))
#define MMA16816(d, a, b) \
    asm volatile("mma.sync.aligned.m16n8k16.row.col.f32.bf16.bf16.f32 " \
        "{%0,%1,%2,%3}, {%4,%5,%6,%7}, {%8,%9}, {%0,%1,%2,%3};" \
        : "+f"((d)[0]), "+f"((d)[1]), "+f"((d)[2]), "+f"((d)[3]) \
        : "r"((a)[0]), "r"((a)[1]), "r"((a)[2]), "r"((a)[3]), "r"((b)[0]), "r"((b)[1]))

__global__ __launch_bounds__(256, 1)
void gemm_mma(const __nv_bfloat16* __restrict__ Ah, const __nv_bfloat16* __restrict__ Al, int lda,
              const __nv_bfloat16* __restrict__ Bh, const __nv_bfloat16* __restrict__ Bl, int ldw,
              float* __restrict__ C, int ldc, const float* __restrict__ bias,
              int Nvalid, int Ktot, int mode)
{
    extern __shared__ __align__(16) char dynsmem[];
    const int tid  = threadIdx.x;
    const int wid  = tid >> 5;
    const int lane = tid & 31;
    const int wm = wid & 1;
    const int wn = wid >> 1;
    const int m0 = blockIdx.y * 128;
    const int n0 = blockIdx.x * 128;
    const int nk = Ktot / (32 * (int)gridDim.z);
    const int kbeg = blockIdx.z * nk * 32;
    const uint32_t sb = smem_u32(dynsmem);

    // ---- cp.async roles: thread t -> row t/2, two 16B col-chunks ----
    const int row = tid >> 1;
    const uint32_t c40 = (uint32_t)(tid & 1) * 2;
    const int brow_g = n0 + row;
    const uint32_t bsz = (brow_g < Nvalid) ? 16u : 0u;
    const size_t wrow = (brow_g < Nvalid) ? (size_t)brow_g : 0;
    const char* pAh = (const char*)(Ah + (size_t)(m0 + row) * lda + kbeg);
    const char* pAl = (const char*)(Al + (size_t)(m0 + row) * lda + kbeg);
    const char* pBh = (const char*)(Bh + wrow * ldw + kbeg);
    const char* pBl = (const char*)(Bl + wrow * ldw + kbeg);
    const uint32_t drow = (uint32_t)row * ROWB;

    auto prefetch = [&](int c) {
        if (c < nk) {
            uint32_t stg = sb + (uint32_t)(c & 3) * STG + drow;
            size_t goff = (size_t)c * 64;
            #pragma unroll
            for (int i = 0; i < 2; i++) {
                uint32_t o16 = (c40 + i) * 16;
                CP_ASYNC(stg + o16,            pAh + goff + o16, 16u);
                CP_ASYNC(stg + PLA + o16,      pAl + goff + o16, 16u);
                CP_ASYNC(stg + 2u * PLA + o16, pBh + goff + o16, bsz);
                CP_ASYNC(stg + 3u * PLA + o16, pBl + goff + o16, bsz);
            }
        }
        CP_COMMIT();
    };

    float d[4][4][4];
    #pragma unroll
    for (int i = 0; i < 4; i++)
        #pragma unroll
        for (int j = 0; j < 4; j++)
            #pragma unroll
            for (int q = 0; q < 4; q++) d[i][j][q] = 0.f;

    // ldmatrix base offsets
    const int arow = wm * 64 + (lane & 15);
    const int asel = lane >> 4;
    const int brow = wn * 32 + (lane >> 4) * 8 + (lane & 7);
    const int bsel = (lane >> 3) & 1;

    prefetch(0); prefetch(1); prefetch(2);

    for (int c = 0; c < nk; c++) {
        CP_WAIT2();
        __syncthreads();
        prefetch(c + 3);

        const uint32_t base = sb + (uint32_t)(c & 3) * STG;
        const uint32_t sAh = base, sAl = base + PLA;
        const uint32_t sBh = base + 2 * PLA, sBl = base + 3 * PLA;

        #pragma unroll
        for (int ks = 0; ks < 2; ks++) {
            uint32_t ah[4][4], al[4][4], bh[4][2], bl[4][2];
            #pragma unroll
            for (int mt = 0; mt < 4; mt++) {
                uint32_t off = (arow + mt * 16) * ROWB + (ks * 2 + asel) * 16;
                LDSM_X4(ah[mt], sAh + off);
                LDSM_X4(al[mt], sAl + off);
            }
            #pragma unroll
            for (int np = 0; np < 2; np++) {
                uint32_t off = (brow + np * 16) * ROWB + (ks * 2 + bsel) * 16;
                uint32_t th[4], tl[4];
                LDSM_X4(th, sBh + off);
                LDSM_X4(tl, sBl + off);
                bh[2 * np][0] = th[0]; bh[2 * np][1] = th[1];
                bh[2 * np + 1][0] = th[2]; bh[2 * np + 1][1] = th[3];
                bl[2 * np][0] = tl[0]; bl[2 * np][1] = tl[1];
                bl[2 * np + 1][0] = tl[2]; bl[2 * np + 1][1] = tl[3];
            }
            #pragma unroll
            for (int mt = 0; mt < 4; mt++)
                #pragma unroll
                for (int nt = 0; nt < 4; nt++) {
                    MMA16816(d[mt][nt], ah[mt], bh[nt]);
                    MMA16816(d[mt][nt], ah[mt], bl[nt]);
                    MMA16816(d[mt][nt], al[mt], bh[nt]);
                }
        }
    }

    // ---- epilogue ----
    const int g = lane >> 2, q = lane & 3;
    #pragma unroll
    for (int mt = 0; mt < 4; mt++) {
        int r0 = m0 + wm * 64 + mt * 16 + g;
        #pragma unroll
        for (int nt = 0; nt < 4; nt++) {
            int c0 = n0 + wn * 32 + nt * 8 + q * 2;
            if (c0 >= Nvalid) continue;
            bool c1v = (c0 + 1) < Nvalid;
            float v00 = d[mt][nt][0], v01 = d[mt][nt][1];
            float v10 = d[mt][nt][2], v11 = d[mt][nt][3];
            float* p0 = C + (size_t)r0 * ldc + c0;
            float* p1 = C + (size_t)(r0 + 8) * ldc + c0;
            if (mode == 2) {
                atomicAdd(p0, v00); if (c1v) atomicAdd(p0 + 1, v01);
                atomicAdd(p1, v10); if (c1v) atomicAdd(p1 + 1, v11);
            } else {
                if (mode == 1) {
                    v00 += bias[c0]; v10 += bias[c0];
                    if (c1v) { v01 += bias[c0 + 1]; v11 += bias[c0 + 1]; }
                } else if (mode == 3) {
                    float b0 = bias[c0], b1 = c1v ? bias[c0 + 1] : 0.f;
                    float t;
                    t = v00 + b0; v00 = (t > 20.f) ? t : log1pf(expf(t));
                    t = v10 + b0; v10 = (t > 20.f) ? t : log1pf(expf(t));
                    t = v01 + b1; v01 = (t > 20.f) ? t : log1pf(expf(t));
                    t = v11 + b1; v11 = (t > 20.f) ? t : log1pf(expf(t));
                }
                if (c1v) {
                    *(float2*)p0 = make_float2(v00, v01);
                    *(float2*)p1 = make_float2(v10, v11);
                } else { *p0 = v00; *p1 = v10; }
            }
        }
    }
}

// ================= elementwise / misc kernels =================
__global__ void im2col_kernel(const float* __restrict__ x) {
    int idx = blockIdx.x * blockDim.x + threadIdx.x;
    if (idx >= NTOK * EMBED) return;
    int col = idx % EMBED;
    int row = idx / EMBED;
    int b = row / LSEQ, l = row % LSEQ;
    int ph = l / 14, pw = l % 14;
    int c = col / 256;
    int i = (col % 256) / 16;
    int j = col % 16;
    size_t src = (((size_t)b * 3 + c) * 224 + (ph * 16 + i)) * 224 + (pw * 16 + j);
    float v = x[src];
    __nv_bfloat16 h = __float2bfloat16(v);
    g_pah[idx] = h;
    g_pal[idx] = __float2bfloat16(v - __bfloat162float(h));
}

__global__ void abcde_kernel(const float* __restrict__ f, const float* __restrict__ w,
                             const float* __restrict__ b) {
    int idx = blockIdx.x * blockDim.x + threadIdx.x;
    if (idx >= BATCH * EMBED) return;
    int bb = idx / EMBED, e = idx % EMBED;
    float s = b[e];
    #pragma unroll
    for (int k = 0; k < 5; k++) s += f[bb * 5 + k] * w[e * 5 + k];
    g_vec[idx] = s;
}

// gather + patch epilogue fused: xm[b,l,c*768+e] = xe[b,src_l,e]+pb[e]+pos[src_l,e]+vec[b,e]
__global__ void gather_kernel(const float* __restrict__ pb, const float* __restrict__ pos) {
    int idx = blockIdx.x * blockDim.x + threadIdx.x;
    if (idx >= NTOK * DIMM) return;
    int e = idx % EMBED;
    int c = (idx / EMBED) & 3;
    int l = (idx / DIMM) % LSEQ;
    int b = idx / (DIMM * LSEQ);
    int src_l = (c == 0) ? g_sp[l] : (c == 1) ? g_ra[l] : (c == 2) ? g_bo[l] : l;
    g_xm[idx] = g_xe[((size_t)b * LSEQ + src_l) * EMBED + e]
              + pb[e] + pos[src_l * EMBED + e] + g_vec[b * EMBED + e];
}

// layernorm; optional input bias; optional fp32 out; optional hi/lo plane out
__global__ void ln_kernel(const float* __restrict__ x, const float* __restrict__ inb,
                          const float* __restrict__ w, const float* __restrict__ b,
                          float* __restrict__ outf,
                          __nv_bfloat16* __restrict__ oh, __nv_bfloat16* __restrict__ ol,
                          int D) {
    int row = blockIdx.x;
    const float* xr = x + (size_t)row * D;
    __shared__ float sh[256];
    __shared__ float s_mean, s_inv;
    int tid = threadIdx.x;
    float s = 0.f;
    for (int i = tid; i < D; i += 256) s += xr[i] + (inb ? inb[i] : 0.f);
    sh[tid] = s; __syncthreads();
    for (int o = 128; o > 0; o >>= 1) { if (tid < o) sh[tid] += sh[tid + o]; __syncthreads(); }
    if (tid == 0) s_mean = sh[0] / (float)D;
    __syncthreads();
    float m = s_mean;
    float v2 = 0.f;
    for (int i = tid; i < D; i += 256) {
        float t = xr[i] + (inb ? inb[i] : 0.f) - m;
        v2 += t * t;
    }
    sh[tid] = v2; __syncthreads();
    for (int o = 128; o > 0; o >>= 1) { if (tid < o) sh[tid] += sh[tid + o]; __syncthreads(); }
    if (tid == 0) s_inv = 1.f / sqrtf(sh[0] / (float)D + 1e-5f);
    __syncthreads();
    float inv = s_inv;
    for (int i = tid; i < D; i += 256) {
        float t = (xr[i] + (inb ? inb[i] : 0.f) - m) * inv;
        float v = t * w[i] + b[i];
        size_t o = (size_t)row * D + i;
        if (outf) outf[o] = v;
        if (oh) {
            __nv_bfloat16 h = __float2bfloat16(v);
            oh[o] = h;
            ol[o] = __float2bfloat16(v - __bfloat162float(h));
        }
    }
}

__global__ void conv_silu_kernel(const float* __restrict__ w, const float* __restrict__ bias) {
    int idx = blockIdx.x * blockDim.x + threadIdx.x;
    if (idx >= NTOK * DINN) return;
    int d = idx % DINN;
    int t = (idx / DINN) % LSEQ;
    int b = idx / (DINN * LSEQ);
    const float* wd = w + (size_t)d * 4;
    float acc = bias[d];
    size_t rb = ((size_t)b * LSEQ) * XRW + d;
    #pragma unroll
    for (int k = 0; k < 4; k++) {
        int tt = t - 3 + k;
        if (tt >= 0) acc = fmaf(wd[k], g_xr[rb + (size_t)tt * XRW], acc);
    }
    float s = acc / (1.f + __expf(-acc));
    g_xs[idx] = s;
    __nv_bfloat16 h = __float2bfloat16(s);
    g_xsh[idx] = h;
    g_xsl[idx] = __float2bfloat16(s - __bfloat162float(h));
}

__global__ void scan_kernel(const float* __restrict__ alog, const float* __restrict__ Dp) {
    int tid = threadIdx.x;
    int n  = tid & 15;
    int ci = tid >> 4;
    int blk = blockIdx.x;
    int b = blk / 384;
    int d = (blk % 384) * 16 + ci;

    float Ac = -__expf(alog[(size_t)d * DST + n]);
    float Dv = Dp[d];
    float st = 0.f;
    size_t base = (size_t)b * LSEQ;
    for (int t = 0; t < LSEQ; t++) {
        size_t row = base + t;
        float dtv = g_dt[row * DINN + d];
        float xv  = g_xs[row * DINN + d];
        float Bv  = g_dbl[row * 224 + 192 + n];
        float Cv  = g_dbl[row * 224 + 208 + n];
        st = fmaf(st, __expf(dtv * Ac), dtv * Bv * xv);
        float yp = st * Cv;
        yp += __shfl_down_sync(0xffffffffu, yp, 8, 16);
        yp += __shfl_down_sync(0xffffffffu, yp, 4, 16);
        yp += __shfl_down_sync(0xffffffffu, yp, 2, 16);
        yp += __shfl_down_sync(0xffffffffu, yp, 1, 16);
        if (n == 0) {
            float r = g_xr[row * XRW + DINN + d];
            float yf = fmaf(xv, Dv, yp);
            yf = yf * (r / (1.f + __expf(-r)));
            __nv_bfloat16 h = __float2bfloat16(yf);
            g_yh[row * DINN + d] = h;
            g_yl[row * DINN + d] = __float2bfloat16(yf - __bfloat162float(h));
        }
    }
}

__global__ void mean_kernel(float* __restrict__ out) {
    int idx = blockIdx.x * blockDim.x + threadIdx.x;
    if (idx >= BATCH * EMBED) return;
    int b = idx / EMBED, e = idx % EMBED;
    float s = 0.f;
    for (int t = 0; t < LSEQ; t++)
        s += g_prln[((size_t)b * LSEQ + t) * EMBED + e];
    out[idx] = s / (float)LSEQ;
}

// ---------------- host: permutation index construction (mirrors numpy) ------
static void build_spiral(int* sp) {
    bool seen[LSEQ] = {false};
    int cnt = 0;
    for (int r = 0; r < 14; r++) {
        int n = (2 * r > 8) ? 2 * r : 8;
        double step = (2.0 * M_PI) / (double)n;
        for (int k = 0; k < n; k++) {
            double ang = (double)k * step;
            int h = (int)(7.0 + (double)r * cos(ang));
            int w = (int)(7.0 + (double)r * sin(ang));
            if (h >= 0 && h < 14 && w >= 0 && w < 14) {
                int i = h * 14 + w;
                if (!seen[i]) { seen[i] = true; sp[cnt++] = i; }
            }
        }
    }
    for (int i = 0; i < LSEQ; i++) if (!seen[i]) sp[cnt++] = i;
}
struct RItem { double d, a; int i; };
static void build_radial(int* ra) {
    RItem items[LSEQ];
    for (int h = 0; h < 14; h++)
        for (int w = 0; w < 14; w++) {
            int i = h * 14 + w;
            double dy = (double)(h - 7), dx = (double)(w - 7);
            items[i].d = sqrt(dy * dy + dx * dx);
            items[i].a = atan2(dy, dx);
            items[i].i = i;
        }
    std::stable_sort(items, items + LSEQ, [](const RItem& x, const RItem& y) {
        if (x.d != y.d) return x.d > y.d;
        return x.a < y.a;
    });
    for (int i = 0; i < LSEQ; i++) ra[i] = items[i].i;
}
static void build_boundary(int* bo) {
    int cnt = 0;
    for (int h = 0; h < 14; h++)
        for (int w = 0; w < 14; w++)
            if (h == 0 || h == 13 || w == 0 || w == 13) bo[cnt++] = h * 14 + w;
    for (int h = 0; h < 14; h++)
        for (int w = 0; w < 14; w++)
            if (!(h == 0 || h == 13 || w == 0 || w == 13)) bo[cnt++] = h * 14 + w;
}

// ---------------- launcher ----------------
static inline int cvt_grid(int n8) {
    int g = (n8 + 255) / 256;
    return g > 4096 ? 4096 : g;
}

extern "C" void kernel_launch(void* const* d_in, const int* in_sizes, int n_in,
                              void* d_out, int out_size) {
    const float* x       = (const float*)d_in[0];
    const float* abf     = (const float*)d_in[1];
    const float* patch_w = (const float*)d_in[2];
    const float* patch_b = (const float*)d_in[3];
    const float* pos     = (const float*)d_in[4];
    const float* aw      = (const float*)d_in[5];
    const float* ab      = (const float*)d_in[6];
    const float* ln_w    = (const float*)d_in[7];
    const float* ln_b    = (const float*)d_in[8];
    const float* inw     = (const float*)d_in[9];
    const float* convw   = (const float*)d_in[10];
    const float* convb   = (const float*)d_in[11];
    const float* xpw     = (const float*)d_in[12];
    const float* dtw     = (const float*)d_in[13];
    const float* alog    = (const float*)d_in[14];
    const float* dpar    = (const float*)d_in[15];
    const float* outw    = (const float*)d_in[16];
    const float* projw   = (const float*)d_in[17];
    const float* projb   = (const float*)d_in[18];
    const float* normw   = (const float*)d_in[19];
    const float* normb   = (const float*)d_in[20];
    const float* dtb     = (const float*)d_in[21];

    static int hsp[LSEQ], hra[LSEQ], hbo[LSEQ];
    build_spiral(hsp);
    build_radial(hra);
    build_boundary(hbo);
    cudaMemcpyToSymbolAsync(g_sp, hsp, sizeof(hsp), 0, cudaMemcpyHostToDevice, 0);
    cudaMemcpyToSymbolAsync(g_ra, hra, sizeof(hra), 0, cudaMemcpyHostToDevice, 0);
    cudaMemcpyToSymbolAsync(g_bo, hbo, sizeof(hbo), 0, cudaMemcpyHostToDevice, 0);

    cudaFuncSetAttribute(gemm_mma, cudaFuncAttributeMaxDynamicSharedMemorySize, GSMEM);

    // symbol addresses
    void *p_xe, *p_xm, *p_xr, *p_dbl, *p_dt, *p_pr, *p_prln;
    cudaGetSymbolAddress(&p_xe, g_xe);
    cudaGetSymbolAddress(&p_xm, g_xm);
    cudaGetSymbolAddress(&p_xr, g_xr);
    cudaGetSymbolAddress(&p_dbl, g_dbl);
    cudaGetSymbolAddress(&p_dt, g_dt);
    cudaGetSymbolAddress(&p_pr, g_pr);
    cudaGetSymbolAddress(&p_prln, g_prln);

    void *pah, *pal, *xlnh, *xlnl, *xsh, *xsl, *yh, *yl, *dblh, *dbll, *xmh, *xml;
    cudaGetSymbolAddress(&pah, g_pah);   cudaGetSymbolAddress(&pal, g_pal);
    cudaGetSymbolAddress(&xlnh, g_xlnh); cudaGetSymbolAddress(&xlnl, g_xlnl);
    cudaGetSymbolAddress(&xsh, g_xsh);   cudaGetSymbolAddress(&xsl, g_xsl);
    cudaGetSymbolAddress(&yh, g_yh);     cudaGetSymbolAddress(&yl, g_yl);
    cudaGetSymbolAddress(&dblh, g_dblh); cudaGetSymbolAddress(&dbll, g_dbll);
    cudaGetSymbolAddress(&xmh, g_xmh);   cudaGetSymbolAddress(&xml, g_xml);

    void *w_ih, *w_il, *w_oh, *w_ol, *w_xh, *w_xl, *w_dh, *w_dl, *w_ph, *w_pl, *w_ch, *w_cl;
    cudaGetSymbolAddress(&w_ih, g_wih); cudaGetSymbolAddress(&w_il, g_wil);
    cudaGetSymbolAddress(&w_oh, g_woh); cudaGetSymbolAddress(&w_ol, g_wol);
    cudaGetSymbolAddress(&w_xh, g_wxh); cudaGetSymbolAddress(&w_xl, g_wxl);
    cudaGetSymbolAddress(&w_dh, g_wdh); cudaGetSymbolAddress(&w_dl, g_wdl);
    cudaGetSymbolAddress(&w_ph, g_wph); cudaGetSymbolAddress(&w_pl, g_wpl);
    cudaGetSymbolAddress(&w_ch, g_wch); cudaGetSymbolAddress(&w_cl, g_wcl);

    const int T256 = 256;
    const int PAD = PADM - NTOK;

    // weight hi/lo splits
    cvt_kernel<<<cvt_grid(SZ_INW / 8), T256>>>((const float4*)inw,   (uint4*)w_ih, (uint4*)w_il, SZ_INW / 8);
    cvt_kernel<<<cvt_grid(SZ_OUTW / 8), T256>>>((const float4*)outw, (uint4*)w_oh, (uint4*)w_ol, SZ_OUTW / 8);
    cvt_kernel<<<cvt_grid(SZ_XPW / 8), T256>>>((const float4*)xpw,   (uint4*)w_xh, (uint4*)w_xl, SZ_XPW / 8);
    cvt_kernel<<<cvt_grid(SZ_DTW / 8), T256>>>((const float4*)dtw,   (uint4*)w_dh, (uint4*)w_dl, SZ_DTW / 8);
    cvt_kernel<<<cvt_grid(SZ_PRW / 8), T256>>>((const float4*)projw, (uint4*)w_ph, (uint4*)w_pl, SZ_PRW / 8);
    cvt_kernel<<<cvt_grid(SZ_PAW / 8), T256>>>((const float4*)patch_w, (uint4*)w_ch, (uint4*)w_cl, SZ_PAW / 8);

    // zero pad rows of activation planes (once) + fp32 targets
    cudaMemsetAsync((__nv_bfloat16*)pah  + (size_t)NTOK * EMBED, 0, (size_t)PAD * EMBED * 2, 0);
    cudaMemsetAsync((__nv_bfloat16*)pal  + (size_t)NTOK * EMBED, 0, (size_t)PAD * EMBED * 2, 0);
    cudaMemsetAsync((__nv_bfloat16*)xlnh + (size_t)NTOK * DIMM,  0, (size_t)PAD * DIMM * 2, 0);
    cudaMemsetAsync((__nv_bfloat16*)xlnl + (size_t)NTOK * DIMM,  0, (size_t)PAD * DIMM * 2, 0);
    cudaMemsetAsync((__nv_bfloat16*)xsh  + (size_t)NTOK * DINN,  0, (size_t)PAD * DINN * 2, 0);
    cudaMemsetAsync((__nv_bfloat16*)xsl  + (size_t)NTOK * DINN,  0, (size_t)PAD * DINN * 2, 0);
    cudaMemsetAsync((__nv_bfloat16*)yh   + (size_t)NTOK * DINN,  0, (size_t)PAD * DINN * 2, 0);
    cudaMemsetAsync((__nv_bfloat16*)yl   + (size_t)NTOK * DINN,  0, (size_t)PAD * DINN * 2, 0);
    cudaMemsetAsync((float*)p_xm + (size_t)NTOK * DIMM, 0, (size_t)PAD * DIMM * 4, 0);
    cudaMemsetAsync(p_xe, 0, (size_t)PADM * EMBED * 4, 0);

    // patch embedding
    im2col_kernel<<<(NTOK * EMBED + T256 - 1) / T256, T256>>>(x);
    abcde_kernel<<<(BATCH * EMBED + T256 - 1) / T256, T256>>>(abf, aw, ab);
    gemm_mma<<<dim3(6, 4, 3), T256, GSMEM>>>(
        (const __nv_bfloat16*)pah, (const __nv_bfloat16*)pal, EMBED,
        (const __nv_bfloat16*)w_ch, (const __nv_bfloat16*)w_cl, EMBED,
        (float*)p_xe, EMBED, nullptr, EMBED, EMBED, 2);
    gather_kernel<<<(NTOK * DIMM + T256 - 1) / T256, T256>>>(patch_b, pos);

    for (int l = 0; l < 2; l++) {
        ln_kernel<<<NTOK, T256>>>((const float*)p_xm, nullptr,
                                  ln_w + (size_t)l * DIMM, ln_b + (size_t)l * DIMM,
                                  nullptr, (__nv_bfloat16*)xlnh, (__nv_bfloat16*)xlnl, DIMM);
        // in_proj -> xr (store)
        gemm_mma<<<dim3(96, 4, 1), T256, GSMEM>>>(
            (const __nv_bfloat16*)xlnh, (const __nv_bfloat16*)xlnl, DIMM,
            (const __nv_bfloat16*)w_ih + (size_t)l * XRW * DIMM,
            (const __nv_bfloat16*)w_il + (size_t)l * XRW * DIMM, DIMM,
            (float*)p_xr, XRW, nullptr, XRW, DIMM, 0);
        conv_silu_kernel<<<(NTOK * DINN + T256 - 1) / T256, T256>>>(
            convw + (size_t)l * DINN * 4, convb + (size_t)l * DINN);
        // x_proj: split-K 12, atomic into dbl
        cudaMemsetAsync(p_dbl, 0, (size_t)PADM * 224 * 4, 0);
        gemm_mma<<<dim3(2, 4, 12), T256, GSMEM>>>(
            (const __nv_bfloat16*)xsh, (const __nv_bfloat16*)xsl, DINN,
            (const __nv_bfloat16*)w_xh + (size_t)l * 224 * DINN,
            (const __nv_bfloat16*)w_xl + (size_t)l * 224 * DINN, DINN,
            (float*)p_dbl, 224, nullptr, 224, DINN, 2);
        cvt_kernel<<<cvt_grid(PADM * 224 / 8), T256>>>((const float4*)p_dbl,
                                                       (uint4*)dblh, (uint4*)dbll, PADM * 224 / 8);
        // dt_proj + softplus(+bias); A = dbl[:, :192] (lda=224)
        gemm_mma<<<dim3(48, 4, 1), T256, GSMEM>>>(
            (const __nv_bfloat16*)dblh, (const __nv_bfloat16*)dbll, 224,
            (const __nv_bfloat16*)w_dh + (size_t)l * DINN * DTR,
            (const __nv_bfloat16*)w_dl + (size_t)l * DINN * DTR, DTR,
            (float*)p_dt, DINN, dtb + (size_t)l * DINN, DINN, DTR, 3);
        scan_kernel<<<768, T256>>>(alog + (size_t)l * DINN * DST,
                                   dpar + (size_t)l * DINN);
        // out_proj residual accumulate into xm, split-K 2, atomic
        gemm_mma<<<dim3(24, 4, 2), T256, GSMEM>>>(
            (const __nv_bfloat16*)yh, (const __nv_bfloat16*)yl, DINN,
            (const __nv_bfloat16*)w_oh + (size_t)l * DIMM * DINN,
            (const __nv_bfloat16*)w_ol + (size_t)l * DIMM * DINN, DINN,
            (float*)p_xm, DIMM, nullptr, DIMM, DINN, 2);
    }

    // final projection
    cvt_kernel<<<cvt_grid(PADM * DIMM / 8), T256>>>((const float4*)p_xm,
                                                    (uint4*)xmh, (uint4*)xml, PADM * DIMM / 8);
    cudaMemsetAsync(p_pr, 0, (size_t)PADM * EMBED * 4, 0);
    gemm_mma<<<dim3(6, 4, 6), T256, GSMEM>>>(
        (const __nv_bfloat16*)xmh, (const __nv_bfloat16*)xml, DIMM,
        (const __nv_bfloat16*)w_ph, (const __nv_bfloat16*)w_pl, DIMM,
        (float*)p_pr, EMBED, nullptr, EMBED, DIMM, 2);
    ln_kernel<<<NTOK, T256>>>((const float*)p_pr, projb, normw, normb,
                              (float*)p_prln, nullptr, nullptr, EMBED);
    mean_kernel<<<(BATCH * EMBED + T256 - 1) / T256, T256>>>((float*)d_out);
}